// round 6
// baseline (speedup 1.0000x reference)
#include <cuda_runtime.h>

#define NTIME 1024
#define NB    65536
#define TPB   128

// Register select helpers (ternary trees keep arrays in registers).
__device__ __forceinline__ float sel7(const float x0, const float x1, const float x2,
                                      const float x3, const float x4, const float x5,
                                      const float x6, int i)
{
    const float a01 = (i & 1) ? x1 : x0;
    const float a23 = (i & 1) ? x3 : x2;
    const float a45 = (i & 1) ? x5 : x4;
    const float lo4 = (i & 2) ? a23 : a01;
    const float hi4 = (i & 2) ? x6  : a45;   // i in {4,5,6}: 6 -> x6
    return (i & 4) ? hi4 : lo4;
}

__device__ __forceinline__ float sel3(const float x0, const float x1, const float x2, int i)
{
    const float a = (i & 1) ? x1 : x0;
    return (i & 2) ? x2 : a;
}

__device__ __forceinline__ float sel5(const float x0, const float x1, const float x2,
                                      const float x3, const float x4, int i)
{
    const float a01 = (i & 1) ? x1 : x0;
    const float a23 = (i & 1) ? x3 : x2;
    const float lo4 = (i & 2) ? a23 : a01;
    return (i & 4) ? x4 : lo4;
}

__global__ void __launch_bounds__(TPB)
bts_interp_kernel(const float* __restrict__ times,
                  const float* __restrict__ values,
                  const float* __restrict__ tq,
                  float* __restrict__ out)
{
    const int b = blockIdx.x * TPB + threadIdx.x;
    const float t = __ldg(&tq[b]);
    const float* col = times + b;

    // ── Round 1 (coalesced): coarse rows 31, 63, ..., 1023. Bucket of 32. ──
    // m = #coarse <= t; lo = last success (= times[32m-1]); hi = first failure
    // (= times[32m+31]).
    int   m  = 0;
    float lo = 0.0f;
    float hi = 0.0f;
#pragma unroll
    for (int chunk = 0; chunk < 4; ++chunk) {
        float x[8];
#pragma unroll
        for (int i = 0; i < 8; ++i)
            x[i] = __ldg(col + (size_t)(32 * (chunk * 8 + i) + 31) * NB);
#pragma unroll
        for (int i = 0; i < 8; ++i) {
            const int idx = chunk * 8 + i;
            if (x[i] <= t) { lo = x[i]; m++; }
            else if (idx == m) { hi = x[i]; }   // first failure only
        }
    }

    int c = m << 5;       // count in [c, c+31]; m==32 -> count == 1024 (wrap path).
    float result;

    if (m < 32) {
        // ── Round 2 (7 independent probes, step 4): bucket 32 -> 4. ──
        // Probe counts c+4..c+28 (rows c+3, c+7, ..., c+27).
        const float p0 = __ldg(col + (size_t)(c + 3)  * NB);
        const float p1 = __ldg(col + (size_t)(c + 7)  * NB);
        const float p2 = __ldg(col + (size_t)(c + 11) * NB);
        const float p3 = __ldg(col + (size_t)(c + 15) * NB);
        const float p4 = __ldg(col + (size_t)(c + 19) * NB);
        const float p5 = __ldg(col + (size_t)(c + 23) * NB);
        const float p6 = __ldg(col + (size_t)(c + 27) * NB);
        const int s = ((p0 <= t) ? 1 : 0) + ((p1 <= t) ? 1 : 0) + ((p2 <= t) ? 1 : 0)
                    + ((p3 <= t) ? 1 : 0) + ((p4 <= t) ? 1 : 0) + ((p5 <= t) ? 1 : 0)
                    + ((p6 <= t) ? 1 : 0);
        if (s > 0) lo = sel7(p0, p1, p2, p3, p4, p5, p6, s - 1); // times[c'-1]
        if (s < 7) hi = sel7(p0, p1, p2, p3, p4, p5, p6, s);     // times[c'+3]
        c += 4 * s;       // count in [c, c+3]

        // ── Round 3 (fused): 3 final probes + 5 speculative values rows. ──
        // Probes: rows c, c+1, c+2 (counts c+1..c+3).
        // Values: rows base..base+4 cover values[count-1] and values[count].
        const int base = (c > 0) ? (c - 1) : 0;     // c==0 only when m==0
        const int off  = (c > 0) ? 0 : 1;           // index shift for clamped base
        const float q0 = __ldg(col + (size_t)(c    ) * NB);
        const float q1 = __ldg(col + (size_t)(c + 1) * NB);
        const float q2 = __ldg(col + (size_t)(c + 2) * NB);
        const float w0 = __ldg(&values[(size_t)(base    ) * NB + b]);
        const float w1 = __ldg(&values[(size_t)(base + 1) * NB + b]);
        const float w2 = __ldg(&values[(size_t)(base + 2) * NB + b]);
        const float w3 = __ldg(&values[(size_t)(base + 3) * NB + b]);
        const float w4 = __ldg(&values[(size_t)(base + 4) * NB + b]);

        const int s2 = ((q0 <= t) ? 1 : 0) + ((q1 <= t) ? 1 : 0) + ((q2 <= t) ? 1 : 0);
        if (s2 > 0) lo = sel3(q0, q1, q2, s2 - 1);  // times[c''-1]
        if (s2 < 3) hi = sel3(q0, q1, q2, s2);      // times[c'']
        c += s2;                                    // final count

        if (c != 0) {
            // va = values[c-1], vb = values[c]; bit-exact bracket lo/hi.
            const int ia = s2 - off;                // >= 0 here (c>0)
            const float va = sel5(w0, w1, w2, w3, w4, ia);
            const float vb = sel5(w0, w1, w2, w3, w4, ia + 1);
            const float s0 = (vb - va) / (hi - lo);
            result = va + s0 * (t - lo);
        } else {
            // count == 0: wrap to iv = 1023, isl = 1022.
            const float tp = __ldg(&times [(size_t)(NTIME - 2) * NB + b]);
            const float tl = __ldg(&times [(size_t)(NTIME - 1) * NB + b]);
            const float vp = __ldg(&values[(size_t)(NTIME - 2) * NB + b]);
            const float vl = __ldg(&values[(size_t)(NTIME - 1) * NB + b]);
            const float s0 = (vl - vp) / (tl - tp);
            result = vl + s0 * (t - tl);
        }
    } else {
        // count == 1024: same wrap as count == 0.
        const float tp = __ldg(&times [(size_t)(NTIME - 2) * NB + b]);
        const float tl = __ldg(&times [(size_t)(NTIME - 1) * NB + b]);
        const float vp = __ldg(&values[(size_t)(NTIME - 2) * NB + b]);
        const float vl = __ldg(&values[(size_t)(NTIME - 1) * NB + b]);
        const float s0 = (vl - vp) / (tl - tp);
        result = vl + s0 * (t - tl);
    }

    out[b] = result;
}

extern "C" void kernel_launch(void* const* d_in, const int* in_sizes, int n_in,
                              void* d_out, int out_size)
{
    const float* times  = (const float*)d_in[0];
    const float* values = (const float*)d_in[1];
    const float* tq     = (const float*)d_in[2];
    float* out = (float*)d_out;

    bts_interp_kernel<<<NB / TPB, TPB>>>(times, values, tq, out);
}

// round 7
// speedup vs baseline: 1.5320x; 1.5320x over previous
#include <cuda_runtime.h>

#define NTIME 1024
#define NB    65536
#define TPB   128

__device__ __forceinline__ float sel3(const float x0, const float x1, const float x2, int i)
{
    const float a = (i & 1) ? x1 : x0;
    return (i & 2) ? x2 : a;
}

__global__ void __launch_bounds__(TPB)
bts_interp_kernel(const float* __restrict__ times,
                  const float* __restrict__ values,
                  const float* __restrict__ tq,
                  float* __restrict__ out)
{
    const int b = blockIdx.x * TPB + threadIdx.x;
    const float t = __ldg(&tq[b]);
    const float* col = times + b;

    // ── Round 1 (coalesced): 64 coarse rows 15, 31, ..., 1023 (every 16th knot).
    // m = #coarse <= t  ->  count in [16m, 16m+16).
    // lo = last success (= times[16m-1]), hi = first failure (= times[16m+15]).
    int   m  = 0;
    float lo = 0.0f;
    float hi = 0.0f;
#pragma unroll
    for (int chunk = 0; chunk < 8; ++chunk) {
        float x[8];
#pragma unroll
        for (int i = 0; i < 8; ++i)
            x[i] = __ldg(col + (size_t)(16 * (chunk * 8 + i) + 15) * NB);
#pragma unroll
        for (int i = 0; i < 8; ++i) {
            const int idx = chunk * 8 + i;
            if (x[i] <= t) { lo = x[i]; m++; }
            else if (idx == m) { hi = x[i]; }   // first failure only
        }
    }

    float result;

    if (m < 64) {
        int c = m << 4;   // count in [c, c+15]

        // ── Round 2: 3 independent probes, step 4 (rows c+3, c+7, c+11). ──
        {
            const float p0 = __ldg(col + (size_t)(c + 3)  * NB);
            const float p1 = __ldg(col + (size_t)(c + 7)  * NB);
            const float p2 = __ldg(col + (size_t)(c + 11) * NB);
            const int s = ((p0 <= t) ? 1 : 0) + ((p1 <= t) ? 1 : 0) + ((p2 <= t) ? 1 : 0);
            if (s > 0) lo = sel3(p0, p1, p2, s - 1);   // times[c'-1]
            if (s < 3) hi = sel3(p0, p1, p2, s);       // times[c'+3]
            c += 4 * s;   // count in [c, c+3]
        }

        // ── Round 3: 3 independent probes, step 1 (rows c, c+1, c+2). ──
        {
            const float q0 = __ldg(col + (size_t)(c    ) * NB);
            const float q1 = __ldg(col + (size_t)(c + 1) * NB);
            const float q2 = __ldg(col + (size_t)(c + 2) * NB);
            const int s2 = ((q0 <= t) ? 1 : 0) + ((q1 <= t) ? 1 : 0) + ((q2 <= t) ? 1 : 0);
            if (s2 > 0) lo = sel3(q0, q1, q2, s2 - 1); // times[c-1]
            if (s2 < 3) hi = sel3(q0, q1, q2, s2);     // times[c]
            c += s2;      // exact count
        }

        if (c != 0) {
            // ── Round 4: the only cold values touches (rows c-1, c). ──
            // lo == times[c-1], hi == times[c] bit-exact from the probe chain.
            const float va = __ldg(&values[(size_t)(c - 1) * NB + b]);
            const float vb = __ldg(&values[(size_t)(c    ) * NB + b]);
            const float s0 = (vb - va) / (hi - lo);
            result = va + s0 * (t - lo);
        } else {
            // count == 0: reference wraps to iv = 1023, isl = 1022.
            const float tp = __ldg(&times [(size_t)(NTIME - 2) * NB + b]);
            const float tl = __ldg(&times [(size_t)(NTIME - 1) * NB + b]);
            const float vp = __ldg(&values[(size_t)(NTIME - 2) * NB + b]);
            const float vl = __ldg(&values[(size_t)(NTIME - 1) * NB + b]);
            const float s0 = (vl - vp) / (tl - tp);
            result = vl + s0 * (t - tl);
        }
    } else {
        // count == 1024: same wrap indices as count == 0.
        const float tp = __ldg(&times [(size_t)(NTIME - 2) * NB + b]);
        const float tl = __ldg(&times [(size_t)(NTIME - 1) * NB + b]);
        const float vp = __ldg(&values[(size_t)(NTIME - 2) * NB + b]);
        const float vl = __ldg(&values[(size_t)(NTIME - 1) * NB + b]);
        const float s0 = (vl - vp) / (tl - tp);
        result = vl + s0 * (t - tl);
    }

    out[b] = result;
}

extern "C" void kernel_launch(void* const* d_in, const int* in_sizes, int n_in,
                              void* d_out, int out_size)
{
    const float* times  = (const float*)d_in[0];
    const float* values = (const float*)d_in[1];
    const float* tq     = (const float*)d_in[2];
    float* out = (float*)d_out;

    bts_interp_kernel<<<NB / TPB, TPB>>>(times, values, tq, out);
}

// round 9
// speedup vs baseline: 1.5731x; 1.0269x over previous
#include <cuda_runtime.h>

#define NTIME 1024
#define NB    65536
#define TPB   128   // 4 warps/block; 16 batches per warp (2 lanes per batch)

__device__ __forceinline__ float sel3(float x0, float x1, float x2, int i)
{
    const float a = (i & 1) ? x1 : x0;
    return (i & 2) ? x2 : a;
}

__global__ void __launch_bounds__(TPB)
bts_interp_kernel(const float* __restrict__ times,
                  const float* __restrict__ values,
                  const float* __restrict__ tq,
                  float* __restrict__ out)
{
    const unsigned FULL = 0xFFFFFFFFu;
    const int lane = threadIdx.x & 31;
    const int warp = threadIdx.x >> 5;
    const int half = lane >> 4;                       // 0 = lower pair half
    const int b    = blockIdx.x * 64 + warp * 16 + (lane & 15);

    const float t = __ldg(&tq[b]);
    const float* col = times + b;

    // ── Coarse (split): 64 rows 15,31,...,1023; half h scans coarse idx h*32..h*32+31.
    int   m_h  = 0;
    float lo_h = 0.0f, hi_h = 0.0f;
#pragma unroll
    for (int chunk = 0; chunk < 4; ++chunk) {
        float x[8];
#pragma unroll
        for (int i = 0; i < 8; ++i) {
            const int j = half * 32 + chunk * 8 + i;          // coarse index 0..63
            x[i] = __ldg(col + (size_t)(16 * j + 15) * NB);
        }
#pragma unroll
        for (int i = 0; i < 8; ++i) {
            const int jl = chunk * 8 + i;                     // local 0..31 (sorted prefix)
            if (x[i] <= t) { lo_h = x[i]; m_h++; }
            else if (jl == m_h) hi_h = x[i];                  // first local failure
        }
    }

    // Merge halves (sorted column => any upper-half success implies lower half full).
    const int   m_o  = __shfl_xor_sync(FULL, m_h,  16);
    const float lo_o = __shfl_xor_sync(FULL, lo_h, 16);
    const float hi_o = __shfl_xor_sync(FULL, hi_h, 16);
    const int   m0 = half ? m_o  : m_h;
    const int   m1 = half ? m_h  : m_o;
    const float lo0 = half ? lo_o : lo_h;
    const float lo1 = half ? lo_h : lo_o;
    const float hi0 = half ? hi_o : hi_h;
    const float hi1 = half ? hi_h : hi_o;

    const int m = m0 + m1;
    float lo = (m1 > 0)  ? lo1 : lo0;   // = times[16m-1]  (valid iff m > 0)
    float hi = (m0 < 32) ? hi0 : hi1;   // = times[16m+15] (valid iff m < 64)

    int c = m << 4;                     // count in [c, c+15]
    const bool hiwrap = (m == 64);      // count == 1024 (both pair halves agree)

    // ── Round 2 (split 2/1): probe rows c+3, c+7, c+11. ──
    {
        int r0 = c + 3, r1 = c + 7, r2 = c + 11;
        if (hiwrap) { r0 = r1 = r2 = NTIME - 1; }   // in-bounds; result discarded
        float pa, pb = 0.0f;
        if (half == 0) { pa = __ldg(col + (size_t)r0 * NB);
                         pb = __ldg(col + (size_t)r2 * NB); }
        else           { pa = __ldg(col + (size_t)r1 * NB); }
        const float ea = __shfl_xor_sync(FULL, pa, 16);
        const float eb = __shfl_xor_sync(FULL, pb, 16);
        const float p0 = half ? ea : pa;
        const float p1 = half ? pa : ea;
        const float p2 = half ? eb : pb;
        const int s = ((p0 <= t) ? 1 : 0) + ((p1 <= t) ? 1 : 0) + ((p2 <= t) ? 1 : 0);
        if (s > 0) lo = sel3(p0, p1, p2, s - 1);
        if (s < 3) hi = sel3(p0, p1, p2, s);
        c += 4 * s;                     // count in [c, c+3]
    }

    // ── Round 3 (split 2/1): probe rows c, c+1, c+2. ──
    {
        int r0 = c, r1 = c + 1, r2 = c + 2;
        if (hiwrap) { r0 = r1 = r2 = NTIME - 1; }
        float qa, qb = 0.0f;
        if (half == 0) { qa = __ldg(col + (size_t)r0 * NB);
                         qb = __ldg(col + (size_t)r2 * NB); }
        else           { qa = __ldg(col + (size_t)r1 * NB); }
        const float ea = __shfl_xor_sync(FULL, qa, 16);
        const float eb = __shfl_xor_sync(FULL, qb, 16);
        const float q0 = half ? ea : qa;
        const float q1 = half ? qa : ea;
        const float q2 = half ? eb : qb;
        const int s2 = ((q0 <= t) ? 1 : 0) + ((q1 <= t) ? 1 : 0) + ((q2 <= t) ? 1 : 0);
        if (s2 > 0) lo = sel3(q0, q1, q2, s2 - 1);  // times[c-1] (exact)
        if (s2 < 3) hi = sel3(q0, q1, q2, s2);      // times[c]   (exact)
        c += s2;                                    // exact count (when !hiwrap)
    }

    // ── Values (split 1/1): rows c-1 / c, BOTH clamped to [0, NTIME-1].
    // (hiwrap lanes have c ≈ 1039 here — clamping keeps the dead loads in-bounds;
    //  wrap lanes never use these values.)
    int ia = c - 1;
    if (ia < 0)        ia = 0;
    if (ia > NTIME - 1) ia = NTIME - 1;
    int ib = c;
    if (ib > NTIME - 1) ib = NTIME - 1;

    float v_mine;
    if (half == 0) v_mine = __ldg(&values[(size_t)ia * NB + b]);
    else           v_mine = __ldg(&values[(size_t)ib * NB + b]);
    const float v_oth = __shfl_xor_sync(FULL, v_mine, 16);

    if (half == 0) {
        const bool wrap = hiwrap || (c == 0);       // count == 1024 or 0
        float result;
        if (!wrap) {
            const float va = v_mine;                // values[c-1]
            const float vb = v_oth;                 // values[c]
            const float s0 = (vb - va) / (hi - lo); // lo/hi bit-exact bracket knots
            result = va + s0 * (t - lo);
        } else {
            // Reference wrap: iv = 1023, isl = 1022.
            const float tp = __ldg(&times [(size_t)(NTIME - 2) * NB + b]);
            const float tl = __ldg(&times [(size_t)(NTIME - 1) * NB + b]);
            const float vp = __ldg(&values[(size_t)(NTIME - 2) * NB + b]);
            const float vl = __ldg(&values[(size_t)(NTIME - 1) * NB + b]);
            const float s0 = (vl - vp) / (tl - tp);
            result = vl + s0 * (t - tl);
        }
        out[b] = result;
    }
}

extern "C" void kernel_launch(void* const* d_in, const int* in_sizes, int n_in,
                              void* d_out, int out_size)
{
    const float* times  = (const float*)d_in[0];
    const float* values = (const float*)d_in[1];
    const float* tq     = (const float*)d_in[2];
    float* out = (float*)d_out;

    // 2 threads per batch: 131072 threads, 1024 blocks of 128.
    bts_interp_kernel<<<(NB * 2) / TPB, TPB>>>(times, values, tq, out);
}